// round 1
// baseline (speedup 1.0000x reference)
#include <cuda_runtime.h>
#include <cstdint>

#define L_SEQ   2048
#define D_DIM   64
#define TILE    128
#define R_BAND  128
#define NTILE   (L_SEQ / TILE)   // 16
#define ZDIM    32               // B*H = 2*16

// Dynamic smem: Qs4[128][16] + Ks4[128][16] float4 = 64 KiB
extern __shared__ float4 smem4[];

__global__ __launch_bounds__(256, 1)
void band_scores_kernel(const float* __restrict__ Q,
                        const float* __restrict__ K,
                        float* __restrict__ out)
{
    const int tj  = blockIdx.x;
    const int ti  = blockIdx.y;
    const int z   = blockIdx.z;
    const int tid = threadIdx.x;

    float* outTile = out + ((size_t)z * L_SEQ + (size_t)ti * TILE) * L_SEQ
                         + (size_t)tj * TILE;

    int dd = ti - tj; if (dd < 0) dd = -dd;

    if (dd > 1) {
        // -------- all-zero tile: pure coalesced write --------
        const float4 zz = make_float4(0.f, 0.f, 0.f, 0.f);
        const int c4 = tid & 31;   // 0..31 float4 cols (128 floats/row)
        const int r0 = tid >> 5;   // 0..7
        #pragma unroll
        for (int p = 0; p < 16; ++p) {
            int r = r0 + (p << 3);
            ((float4*)(outTile + (size_t)r * L_SEQ))[c4] = zz;
        }
        return;
    }

    // -------- in-band tile: 128x128 GEMM over D=64 --------
    float4* Qs4 = smem4;
    float4* Ks4 = smem4 + TILE * 16;

    const float* Qg = Q + ((size_t)z * L_SEQ + (size_t)ti * TILE) * D_DIM;
    const float* Kg = K + ((size_t)z * L_SEQ + (size_t)tj * TILE) * D_DIM;

    // 128 rows x 16 float4 each; swizzle kq' = kq ^ ((row>>3)&7)
    #pragma unroll
    for (int p = 0; p < 8; ++p) {
        int idx = tid + p * 256;     // 0..2047
        int row = idx >> 4;
        int kq  = idx & 15;
        int swz = kq ^ ((row >> 3) & 7);
        Qs4[row * 16 + swz] = ((const float4*)Qg)[idx];
        Ks4[row * 16 + swz] = ((const float4*)Kg)[idx];
    }
    __syncthreads();

    const int ty = tid >> 4;   // 0..15 -> rows 8*ty .. 8*ty+7
    const int tx = tid & 15;   // 0..15 -> cols {4tx..4tx+3} and {64+4tx..+3}

    float acc[8][8];
    #pragma unroll
    for (int r = 0; r < 8; ++r)
        #pragma unroll
        for (int c = 0; c < 8; ++c) acc[r][c] = 0.f;

    const int qsw = ty & 7;

    #pragma unroll
    for (int kq = 0; kq < 16; ++kq) {
        float4 qv[8];
        #pragma unroll
        for (int r = 0; r < 8; ++r)
            qv[r] = Qs4[(8 * ty + r) * 16 + (kq ^ qsw)];

        float4 bv[8];
        #pragma unroll
        for (int c = 0; c < 4; ++c) {
            int rowA = 4 * tx + c;
            int rowB = 64 + 4 * tx + c;
            bv[c]     = Ks4[rowA * 16 + (kq ^ ((rowA >> 3) & 7))];
            bv[4 + c] = Ks4[rowB * 16 + (kq ^ ((rowB >> 3) & 7))];
        }

        #pragma unroll
        for (int r = 0; r < 8; ++r)
            #pragma unroll
            for (int c = 0; c < 8; ++c) {
                acc[r][c] += qv[r].x * bv[c].x;
                acc[r][c] += qv[r].y * bv[c].y;
                acc[r][c] += qv[r].z * bv[c].z;
                acc[r][c] += qv[r].w * bv[c].w;
            }
    }

    // -------- epilogue: band mask + float4 stores --------
    const int gi0 = ti * TILE + 8 * ty;
    const int jA0 = tj * TILE + 4 * tx;
    const int jB0 = tj * TILE + 64 + 4 * tx;

    #pragma unroll
    for (int r = 0; r < 8; ++r) {
        const int gi = gi0 + r;
        float* orow = outTile + (size_t)(8 * ty + r) * L_SEQ;

        float4 vA, vB;
        {
            int d0 = gi - (jA0 + 0); if (d0 < 0) d0 = -d0;
            int d1 = gi - (jA0 + 1); if (d1 < 0) d1 = -d1;
            int d2 = gi - (jA0 + 2); if (d2 < 0) d2 = -d2;
            int d3 = gi - (jA0 + 3); if (d3 < 0) d3 = -d3;
            vA.x = (d0 <= R_BAND) ? acc[r][0] : 0.f;
            vA.y = (d1 <= R_BAND) ? acc[r][1] : 0.f;
            vA.z = (d2 <= R_BAND) ? acc[r][2] : 0.f;
            vA.w = (d3 <= R_BAND) ? acc[r][3] : 0.f;
        }
        {
            int d0 = gi - (jB0 + 0); if (d0 < 0) d0 = -d0;
            int d1 = gi - (jB0 + 1); if (d1 < 0) d1 = -d1;
            int d2 = gi - (jB0 + 2); if (d2 < 0) d2 = -d2;
            int d3 = gi - (jB0 + 3); if (d3 < 0) d3 = -d3;
            vB.x = (d0 <= R_BAND) ? acc[r][4] : 0.f;
            vB.y = (d1 <= R_BAND) ? acc[r][5] : 0.f;
            vB.z = (d2 <= R_BAND) ? acc[r][6] : 0.f;
            vB.w = (d3 <= R_BAND) ? acc[r][7] : 0.f;
        }

        ((float4*)orow)[tx]          = vA;  // cols 4tx..4tx+3
        ((float4*)(orow + 64))[tx]   = vB;  // cols 64+4tx..+3
    }
}

extern "C" void kernel_launch(void* const* d_in, const int* in_sizes, int n_in,
                              void* d_out, int out_size)
{
    const float* Q  = (const float*)d_in[0];
    const float* K  = (const float*)d_in[1];
    float*       out = (float*)d_out;

    cudaFuncSetAttribute(band_scores_kernel,
                         cudaFuncAttributeMaxDynamicSharedMemorySize,
                         64 * 1024);

    dim3 grid(NTILE, NTILE, ZDIM);
    band_scores_kernel<<<grid, 256, 64 * 1024>>>(Q, K, out);
}

// round 2
// speedup vs baseline: 1.1761x; 1.1761x over previous
#include <cuda_runtime.h>
#include <cstdint>

#define L_SEQ   2048
#define D_DIM   64
#define TILE    128
#define R_BAND  128
#define NTILE   (L_SEQ / TILE)   // 16
#define ZDIM    32               // B*H = 2*16

// Dynamic smem: Qs4[128][16] + Ks4[128][16] float4 = 64 KiB
extern __shared__ float4 smem4[];

__global__ __launch_bounds__(256, 2)
void band_scores_kernel(const float* __restrict__ Q,
                        const float* __restrict__ K,
                        float* __restrict__ out)
{
    const int tj  = blockIdx.x;
    const int ti  = blockIdx.y;
    const int z   = blockIdx.z;
    const int tid = threadIdx.x;

    float* outTile = out + ((size_t)z * L_SEQ + (size_t)ti * TILE) * L_SEQ
                         + (size_t)tj * TILE;

    int dd = ti - tj; if (dd < 0) dd = -dd;

    if (dd > 1) {
        // -------- all-zero tile: pure coalesced write --------
        const float4 zz = make_float4(0.f, 0.f, 0.f, 0.f);
        const int c4 = tid & 31;   // 0..31 float4 cols (128 floats/row)
        const int r0 = tid >> 5;   // 0..7
        #pragma unroll
        for (int p = 0; p < 16; ++p) {
            int r = r0 + (p << 3);
            ((float4*)(outTile + (size_t)r * L_SEQ))[c4] = zz;
        }
        return;
    }

    // -------- in-band tile: 128x128 GEMM over D=64 --------
    float4* Qs4 = smem4;
    float4* Ks4 = smem4 + TILE * 16;

    const float* Qg = Q + ((size_t)z * L_SEQ + (size_t)ti * TILE) * D_DIM;
    const float* Kg = K + ((size_t)z * L_SEQ + (size_t)tj * TILE) * D_DIM;

    // 128 rows x 16 float4 each; swizzle kq' = kq ^ ((row>>3)&7)
    #pragma unroll
    for (int p = 0; p < 8; ++p) {
        int idx = tid + p * 256;     // 0..2047
        int row = idx >> 4;
        int kq  = idx & 15;
        int swz = kq ^ ((row >> 3) & 7);
        Qs4[row * 16 + swz] = ((const float4*)Qg)[idx];
        Ks4[row * 16 + swz] = ((const float4*)Kg)[idx];
    }
    __syncthreads();

    const int ty = tid >> 4;   // 0..15 -> rows 8*ty .. 8*ty+7
    const int tx = tid & 15;   // 0..15 -> cols {4tx..4tx+3} and {64+4tx..+3}

    float acc[8][8];
    #pragma unroll
    for (int r = 0; r < 8; ++r)
        #pragma unroll
        for (int c = 0; c < 8; ++c) acc[r][c] = 0.f;

    const int qsw = ty & 7;

    #pragma unroll
    for (int kq = 0; kq < 16; ++kq) {
        float4 qv[8];
        #pragma unroll
        for (int r = 0; r < 8; ++r)
            qv[r] = Qs4[(8 * ty + r) * 16 + (kq ^ qsw)];

        // consume K columns one float4 at a time (low register pressure)
        #pragma unroll
        for (int c = 0; c < 8; ++c) {
            int rowK = (c < 4) ? (4 * tx + c) : (64 + 4 * tx + (c - 4));
            float4 bv = Ks4[rowK * 16 + (kq ^ ((rowK >> 3) & 7))];
            #pragma unroll
            for (int r = 0; r < 8; ++r) {
                acc[r][c] += qv[r].x * bv.x;
                acc[r][c] += qv[r].y * bv.y;
                acc[r][c] += qv[r].z * bv.z;
                acc[r][c] += qv[r].w * bv.w;
            }
        }
    }
    __syncthreads();

    // -------- epilogue --------
    if (ti == tj) {
        // whole tile is in-band (|i-j| <= 127 <= 128): no masking
        #pragma unroll
        for (int r = 0; r < 8; ++r) {
            float* orow = outTile + (size_t)(8 * ty + r) * L_SEQ;
            float4 vA = make_float4(acc[r][0], acc[r][1], acc[r][2], acc[r][3]);
            float4 vB = make_float4(acc[r][4], acc[r][5], acc[r][6], acc[r][7]);
            ((float4*)orow)[tx]        = vA;
            ((float4*)(orow + 64))[tx] = vB;
        }
        return;
    }

    // dd == 1: partial band, mask per element
    const int gi0 = ti * TILE + 8 * ty;
    const int jA0 = tj * TILE + 4 * tx;
    const int jB0 = tj * TILE + 64 + 4 * tx;

    #pragma unroll
    for (int r = 0; r < 8; ++r) {
        const int gi = gi0 + r;
        float* orow = outTile + (size_t)(8 * ty + r) * L_SEQ;

        float4 vA, vB;
        {
            int d0 = gi - (jA0 + 0); if (d0 < 0) d0 = -d0;
            int d1 = gi - (jA0 + 1); if (d1 < 0) d1 = -d1;
            int d2 = gi - (jA0 + 2); if (d2 < 0) d2 = -d2;
            int d3 = gi - (jA0 + 3); if (d3 < 0) d3 = -d3;
            vA.x = (d0 <= R_BAND) ? acc[r][0] : 0.f;
            vA.y = (d1 <= R_BAND) ? acc[r][1] : 0.f;
            vA.z = (d2 <= R_BAND) ? acc[r][2] : 0.f;
            vA.w = (d3 <= R_BAND) ? acc[r][3] : 0.f;
        }
        {
            int d0 = gi - (jB0 + 0); if (d0 < 0) d0 = -d0;
            int d1 = gi - (jB0 + 1); if (d1 < 0) d1 = -d1;
            int d2 = gi - (jB0 + 2); if (d2 < 0) d2 = -d2;
            int d3 = gi - (jB0 + 3); if (d3 < 0) d3 = -d3;
            vB.x = (d0 <= R_BAND) ? acc[r][4] : 0.f;
            vB.y = (d1 <= R_BAND) ? acc[r][5] : 0.f;
            vB.z = (d2 <= R_BAND) ? acc[r][6] : 0.f;
            vB.w = (d3 <= R_BAND) ? acc[r][7] : 0.f;
        }

        ((float4*)orow)[tx]        = vA;
        ((float4*)(orow + 64))[tx] = vB;
    }
}

extern "C" void kernel_launch(void* const* d_in, const int* in_sizes, int n_in,
                              void* d_out, int out_size)
{
    const float* Q  = (const float*)d_in[0];
    const float* K  = (const float*)d_in[1];
    float*       out = (float*)d_out;

    cudaFuncSetAttribute(band_scores_kernel,
                         cudaFuncAttributeMaxDynamicSharedMemorySize,
                         64 * 1024);

    dim3 grid(NTILE, NTILE, ZDIM);
    band_scores_kernel<<<grid, 256, 64 * 1024>>>(Q, K, out);
}

// round 3
// speedup vs baseline: 1.2310x; 1.0467x over previous
#include <cuda_runtime.h>
#include <cstdint>

#define L_SEQ   2048
#define D_DIM   64
#define TILE    128
#define R_BAND  128
#define NTILE   (L_SEQ / TILE)   // 16
#define ZDIM    32               // B*H = 2*16
#define KT_S    132              // Kt row stride in floats (128 + pad, mult of 4)

// Dynamic smem: Qs4[128][16] float4 (32 KiB) + Kt[64][132] float (33 KiB)
extern __shared__ float4 smem4[];

__device__ __forceinline__ void fma2(unsigned long long& d,
                                     unsigned long long a,
                                     unsigned long long b)
{
    asm("fma.rn.f32x2 %0, %1, %2, %0;" : "+l"(d) : "l"(a), "l"(b));
}

__device__ __forceinline__ unsigned long long dup2(float v)
{
    unsigned long long r;
    asm("mov.b64 %0, {%1, %1};" : "=l"(r) : "f"(v));
    return r;
}

__device__ __forceinline__ float2 unpack2(unsigned long long v)
{
    float2 f;
    asm("mov.b64 {%0, %1}, %2;" : "=f"(f.x), "=f"(f.y) : "l"(v));
    return f;
}

__global__ __launch_bounds__(256, 2)
void band_scores_kernel(const float* __restrict__ Q,
                        const float* __restrict__ K,
                        float* __restrict__ out)
{
    const int tj  = blockIdx.x;
    const int ti  = blockIdx.y;
    const int z   = blockIdx.z;
    const int tid = threadIdx.x;

    float* outTile = out + ((size_t)z * L_SEQ + (size_t)ti * TILE) * L_SEQ
                         + (size_t)tj * TILE;

    int dd = ti - tj; if (dd < 0) dd = -dd;

    if (dd > 1) {
        // -------- all-zero tile: pure coalesced write --------
        const float4 zz = make_float4(0.f, 0.f, 0.f, 0.f);
        const int c4 = tid & 31;   // 0..31 float4 cols
        const int r0 = tid >> 5;   // 0..7
        #pragma unroll
        for (int p = 0; p < 16; ++p) {
            int r = r0 + (p << 3);
            ((float4*)(outTile + (size_t)r * L_SEQ))[c4] = zz;
        }
        return;
    }

    // -------- in-band tile: 128x128 GEMM over D=64, packed f32x2 FMA ------
    float4* Qs4 = smem4;                              // [128][16] swizzled
    float*  Kt  = (float*)(smem4 + TILE * 16);        // [64][KT_S] transposed

    const float* Qg = Q + ((size_t)z * L_SEQ + (size_t)ti * TILE) * D_DIM;
    const float* Kg = K + ((size_t)z * L_SEQ + (size_t)tj * TILE) * D_DIM;

    // Q fill: row-major, swizzled kq' = kq ^ ((row>>3)&7)
    #pragma unroll
    for (int p = 0; p < 8; ++p) {
        int idx = tid + p * 256;     // 0..2047
        int row = idx >> 4;
        int kq  = idx & 15;
        Qs4[row * 16 + (kq ^ ((row >> 3) & 7))] = ((const float4*)Qg)[idx];
    }
    // K fill: transposed Kt[k][c] = K[c][k]
    #pragma unroll
    for (int p = 0; p < 8; ++p) {
        int idx = tid + p * 256;     // 0..2047
        int c   = idx >> 4;          // K row (output column)
        int kq  = idx & 15;
        float4 v = ((const float4*)Kg)[idx];
        float* dst = &Kt[(4 * kq) * KT_S + c];
        dst[0 * KT_S] = v.x;
        dst[1 * KT_S] = v.y;
        dst[2 * KT_S] = v.z;
        dst[3 * KT_S] = v.w;
    }
    __syncthreads();

    const int ty = tid >> 4;   // 0..15 -> rows 8*ty .. 8*ty+7
    const int tx = tid & 15;   // 0..15 -> cols {4tx..+3} and {64+4tx..+3}
    const int qsw = ty & 7;

    // acc2[r][p]: p=0 -> cols (4tx,4tx+1), p=1 -> (4tx+2,4tx+3),
    //             p=2 -> (64+4tx,+1),     p=3 -> (64+4tx+2,+3)
    unsigned long long acc2[8][4];
    #pragma unroll
    for (int r = 0; r < 8; ++r)
        #pragma unroll
        for (int p = 0; p < 4; ++p) acc2[r][p] = 0ULL;

    #pragma unroll 4
    for (int kq = 0; kq < 16; ++kq) {
        // b pairs for 4 k's: Kt[k][4tx..4tx+3] and Kt[k][64+4tx..+3]
        ulonglong2 bA[4], bB[4];
        #pragma unroll
        for (int j = 0; j < 4; ++j) {
            const float* base = &Kt[(4 * kq + j) * KT_S + 4 * tx];
            bA[j] = *(const ulonglong2*)base;
            bB[j] = *(const ulonglong2*)(base + 64);
        }
        #pragma unroll
        for (int r = 0; r < 8; ++r) {
            float4 qv = Qs4[(8 * ty + r) * 16 + (kq ^ qsw)];
            #pragma unroll
            for (int j = 0; j < 4; ++j) {
                float q = (j == 0) ? qv.x : (j == 1) ? qv.y
                        : (j == 2) ? qv.z : qv.w;
                unsigned long long q2 = dup2(q);
                fma2(acc2[r][0], q2, bA[j].x);
                fma2(acc2[r][1], q2, bA[j].y);
                fma2(acc2[r][2], q2, bB[j].x);
                fma2(acc2[r][3], q2, bB[j].y);
            }
        }
    }
    __syncthreads();

    // -------- epilogue --------
    if (ti == tj) {
        // whole tile in-band (|i-j| <= 127 <= 128): no masking
        #pragma unroll
        for (int r = 0; r < 8; ++r) {
            float* orow = outTile + (size_t)(8 * ty + r) * L_SEQ;
            float2 p0 = unpack2(acc2[r][0]);
            float2 p1 = unpack2(acc2[r][1]);
            float2 p2 = unpack2(acc2[r][2]);
            float2 p3 = unpack2(acc2[r][3]);
            ((float4*)orow)[tx]        = make_float4(p0.x, p0.y, p1.x, p1.y);
            ((float4*)(orow + 64))[tx] = make_float4(p2.x, p2.y, p3.x, p3.y);
        }
        return;
    }

    // dd == 1: partial band, mask per element
    const int gi0 = ti * TILE + 8 * ty;
    const int jA0 = tj * TILE + 4 * tx;
    const int jB0 = tj * TILE + 64 + 4 * tx;

    #pragma unroll
    for (int r = 0; r < 8; ++r) {
        const int gi = gi0 + r;
        float* orow = outTile + (size_t)(8 * ty + r) * L_SEQ;

        float2 p0 = unpack2(acc2[r][0]);
        float2 p1 = unpack2(acc2[r][1]);
        float2 p2 = unpack2(acc2[r][2]);
        float2 p3 = unpack2(acc2[r][3]);

        float4 vA, vB;
        {
            int d0 = gi - (jA0 + 0); if (d0 < 0) d0 = -d0;
            int d1 = gi - (jA0 + 1); if (d1 < 0) d1 = -d1;
            int d2 = gi - (jA0 + 2); if (d2 < 0) d2 = -d2;
            int d3 = gi - (jA0 + 3); if (d3 < 0) d3 = -d3;
            vA.x = (d0 <= R_BAND) ? p0.x : 0.f;
            vA.y = (d1 <= R_BAND) ? p0.y : 0.f;
            vA.z = (d2 <= R_BAND) ? p1.x : 0.f;
            vA.w = (d3 <= R_BAND) ? p1.y : 0.f;
        }
        {
            int d0 = gi - (jB0 + 0); if (d0 < 0) d0 = -d0;
            int d1 = gi - (jB0 + 1); if (d1 < 0) d1 = -d1;
            int d2 = gi - (jB0 + 2); if (d2 < 0) d2 = -d2;
            int d3 = gi - (jB0 + 3); if (d3 < 0) d3 = -d3;
            vB.x = (d0 <= R_BAND) ? p2.x : 0.f;
            vB.y = (d1 <= R_BAND) ? p2.y : 0.f;
            vB.z = (d2 <= R_BAND) ? p3.x : 0.f;
            vB.w = (d3 <= R_BAND) ? p3.y : 0.f;
        }

        ((float4*)orow)[tx]        = vA;
        ((float4*)(orow + 64))[tx] = vB;
    }
}

extern "C" void kernel_launch(void* const* d_in, const int* in_sizes, int n_in,
                              void* d_out, int out_size)
{
    const float* Q  = (const float*)d_in[0];
    const float* K  = (const float*)d_in[1];
    float*       out = (float*)d_out;

    const int smem_bytes = TILE * 16 * 16 + 64 * KT_S * 4;  // 32768 + 33792

    cudaFuncSetAttribute(band_scores_kernel,
                         cudaFuncAttributeMaxDynamicSharedMemorySize,
                         smem_bytes);

    dim3 grid(NTILE, NTILE, ZDIM);
    band_scores_kernel<<<grid, 256, smem_bytes>>>(Q, K, out);
}